// round 12
// baseline (speedup 1.0000x reference)
#include <cuda_runtime.h>
#include <cuda_bf16.h>
#include <cstdint>

#define LSEQ 2048
#define DM   1024
#define DI   2048
#define DS   16

// ---------------- scratch ----------------
__device__ float g_xres[LSEQ * 2 * DI];   // G1 out (x | res), fp32
__device__ float g_xconv[LSEQ * DI];      // conv+silu, fp32
__device__ float g_xdbl[LSEQ * 96];       // x_proj out, fp32 (B,C for scan)
__device__ float g_delta[LSEQ * DI];      // softplus delta, fp32
__device__ float g_u_t[LSEQ * DM];        // rmsnorm out, tf32-rounded
__device__ float g_dr_t[LSEQ * 64];       // delta_r, tf32-rounded
__device__ float g_y_t[LSEQ * DI];        // scan out, tf32-rounded
// tf32-rounded weights, TRANSPOSED to [N][K]
__device__ float g_w1t[2 * DI * DM];
__device__ float g_w2t[96 * DM];
__device__ float g_w3t[DI * 64];
__device__ float g_w4t[DM * DI];

__device__ __forceinline__ float softplus_f(float x) {
    return fmaxf(x, 0.f) + log1pf(__expf(-fabsf(x)));
}
__device__ __forceinline__ float tf32r(float x) {
    uint32_t r;
    asm("cvt.rna.tf32.f32 %0, %1;" : "=r"(r) : "f"(x));
    return __uint_as_float(r);
}
__device__ __forceinline__ uint32_t smem_to_u32(const void* p) {
    uint32_t a;
    asm("{ .reg .u64 t; cvta.to.shared.u64 t, %1; cvt.u32.u64 %0, t; }" : "=r"(a) : "l"(p));
    return a;
}
__device__ __forceinline__ void ldsm4(uint32_t* r, uint32_t addr) {
    asm volatile("ldmatrix.sync.aligned.m8n8.x4.shared.b16 {%0,%1,%2,%3}, [%4];"
                 : "=r"(r[0]), "=r"(r[1]), "=r"(r[2]), "=r"(r[3]) : "r"(addr));
}
__device__ __forceinline__ void mma_tf32(float* c, const uint32_t* a, uint32_t b0, uint32_t b1) {
    asm volatile("mma.sync.aligned.m16n8k8.row.col.f32.tf32.tf32.f32 "
                 "{%0,%1,%2,%3}, {%4,%5,%6,%7}, {%8,%9}, {%0,%1,%2,%3};"
                 : "+f"(c[0]), "+f"(c[1]), "+f"(c[2]), "+f"(c[3])
                 : "r"(a[0]), "r"(a[1]), "r"(a[2]), "r"(a[3]), "r"(b0), "r"(b1));
}
__device__ __forceinline__ void cp16(uint32_t dst, const void* src, int sz) {
    asm volatile("cp.async.cg.shared.global [%0], [%1], 16, %2;" :: "r"(dst), "l"(src), "r"(sz));
}
#define CP_COMMIT() asm volatile("cp.async.commit_group;" ::: "memory")
#define CP_WAIT1()  asm volatile("cp.async.wait_group 1;" ::: "memory")

// ---------------- tiled transpose + tf32 round: W[K][N] -> Wt[N][K] ----------------
__global__ void __launch_bounds__(256) conv_tr(const float* __restrict__ src,
                                               float* __restrict__ dst, int K, int N) {
    __shared__ float tile[32][33];
    int n0 = blockIdx.x * 32, k0 = blockIdx.y * 32;
    int tx = threadIdx.x & 31, ty = threadIdx.x >> 5;  // 32 x 8
    #pragma unroll
    for (int j = 0; j < 4; ++j)
        tile[ty + j * 8][tx] = tf32r(src[(size_t)(k0 + ty + j * 8) * N + n0 + tx]);
    __syncthreads();
    #pragma unroll
    for (int j = 0; j < 4; ++j)
        dst[(size_t)(n0 + ty + j * 8) * K + k0 + tx] = tile[tx][ty + j * 8];
}

// ---------------- tf32 HMMA GEMM, templated N-tile, n-major B, all-ldsm ----------------
// NTILE=256: tile 128x256, warp 64x64, occ 1 (higher reuse — L2-BW-bound fix).
// NTILE=128: tile 128x128, warp 64x32, occ 2.
// A smem [128 m][36 w], B smem [NTILE n][36 w]; Bt gmem pre-transposed [N][K].
// epi: 0 plain, 1 +extra[r*lde+c], 2 softplus(acc+extra[c]), 3 plain + dr_t (c<64)
template <int NTILE, int MINB>
__global__ void __launch_bounds__(256, MINB) hgemm(
    const float* __restrict__ A, int lda,
    const float* Bt, int ldbt,
    float* C, int ldc, const float* __restrict__ extra, int lde,
    int K, int n_real, int epi, int nsplit,
    const float* B2t, int ldb2t, float* C2, int ldc2, int n2, int epi2)
{
    extern __shared__ char sm[];
    constexpr int STRW = 36;                 // words per row
    constexpr int STRB = STRW * 4;           // 144 bytes
    constexpr int APL  = 128 * STRB;         // A plane: 18432
    constexpr int BPL  = NTILE * STRB;       // B plane
    constexpr int STG  = APL + BPL;          // stage bytes
    constexpr int NTI  = NTILE / 32;         // 8-col n-tiles per warp (8 or 4)
    constexpr int ITB  = NTILE / 32;         // B loader iterations

    int tid = threadIdx.x, wid = tid >> 5, lane = tid & 31;
    int bxi = blockIdx.x;
    int bx;
    if (bxi >= nsplit) {
        Bt = B2t; ldbt = ldb2t; C = C2; ldc = ldc2;
        n_real = n2; epi = epi2; bx = (bxi - nsplit) * NTILE;
    } else {
        bx = bxi * NTILE;
    }
    int by = blockIdx.y * 128;
    int wm = (wid >> 2) * 64, wn = (wid & 3) * (NTILE / 4);
    uint32_t smb = smem_to_u32(sm);

    float acc[4][NTI][4];
    #pragma unroll
    for (int i = 0; i < 4; ++i)
        #pragma unroll
        for (int j = 0; j < NTI; ++j)
            #pragma unroll
            for (int r = 0; r < 4; ++r) acc[i][j][r] = 0.f;

    int T = K >> 5;

    auto load_stage = [&](int s) {
        uint32_t base = smb + (s % 3) * STG;
        int kb = s << 5;
        // A: 128 m-rows x 8 chunks
        #pragma unroll
        for (int i = 0; i < 4; ++i) {
            int pid = i * 256 + tid;
            int row = pid >> 3, ch = pid & 7;
            cp16(base + row * STRB + ch * 16,
                 A + (size_t)(by + row) * lda + kb + ch * 4, 16);
        }
        // B: NTILE n-rows x 8 chunks (k-contiguous in Bt)
        #pragma unroll
        for (int i = 0; i < ITB; ++i) {
            int pid = i * 256 + tid;
            int row = pid >> 3, ch = pid & 7;
            int n = bx + row;
            bool v = n < n_real;
            const float* src = v ? (Bt + (size_t)n * ldbt + kb + ch * 4) : Bt;
            cp16(base + APL + row * STRB + ch * 16, src, v ? 16 : 0);
        }
    };

    load_stage(0); CP_COMMIT();
    if (T > 1) { load_stage(1); }
    CP_COMMIT();

    // A ldsm lane addressing (row-major m16k8 tiles)
    int arow = wm + (lane & 15);
    int acol4 = (lane >> 4) << 2;             // 0 or 4 words
    // B ldsm lane addressing (n-major): grp = lane>>3
    int bgrp = lane >> 3, brr = lane & 7;
    int bcol = (bgrp >> 1) * 8 + brr;         // 0..15 within 16-col group
    uint32_t bko = (uint32_t)((bgrp & 1) * 16);

    for (int s = 0; s < T; ++s) {
        CP_WAIT1();
        __syncthreads();
        if (s + 2 < T) load_stage(s + 2);
        CP_COMMIT();

        uint32_t bA = smb + (s % 3) * STG;
        uint32_t abase = bA + (uint32_t)(arow * STRW + acol4) * 4;
        uint32_t bbase = bA + APL + (uint32_t)((wn + bcol) * STRB) + bko;

        #pragma unroll
        for (int q = 0; q < 4; ++q) {
            uint32_t a[4][4];
            #pragma unroll
            for (int mt = 0; mt < 4; ++mt)
                ldsm4(a[mt], abase + (uint32_t)(mt * 16 * STRB + q * 32));
            uint32_t bf[NTI / 2][4];
            #pragma unroll
            for (int j = 0; j < NTI / 2; ++j)
                ldsm4(bf[j], bbase + (uint32_t)(j * 16 * STRB + q * 32));
            #pragma unroll
            for (int mt = 0; mt < 4; ++mt)
                #pragma unroll
                for (int j = 0; j < NTI / 2; ++j) {
                    mma_tf32(acc[mt][2 * j],     a[mt], bf[j][0], bf[j][1]);
                    mma_tf32(acc[mt][2 * j + 1], a[mt], bf[j][2], bf[j][3]);
                }
        }
    }

    // ---- epilogue ----
    #pragma unroll
    for (int mt = 0; mt < 4; ++mt) {
        #pragma unroll
        for (int nt = 0; nt < NTI; ++nt) {
            int row0 = by + wm + mt * 16 + (lane >> 2);
            int col  = bx + wn + nt * 8 + (lane & 3) * 2;
            if (col < n_real) {
                float* a = acc[mt][nt];
                float2 v0 = make_float2(a[0], a[1]);
                float2 v1 = make_float2(a[2], a[3]);
                if (epi == 1) {
                    float2 e0 = *(const float2*)(extra + (size_t)row0 * lde + col);
                    float2 e1 = *(const float2*)(extra + (size_t)(row0 + 8) * lde + col);
                    v0.x += e0.x; v0.y += e0.y;
                    v1.x += e1.x; v1.y += e1.y;
                } else if (epi == 2) {
                    float b0 = extra[col], b1 = extra[col + 1];
                    v0.x = softplus_f(v0.x + b0);
                    v0.y = softplus_f(v0.y + b1);
                    v1.x = softplus_f(v1.x + b0);
                    v1.y = softplus_f(v1.y + b1);
                }
                *(float2*)(C + (size_t)row0 * ldc + col)       = v0;
                *(float2*)(C + (size_t)(row0 + 8) * ldc + col) = v1;
                if (epi == 3 && col < 64) {
                    g_dr_t[row0 * 64 + col]           = tf32r(v0.x);
                    g_dr_t[row0 * 64 + col + 1]       = tf32r(v0.y);
                    g_dr_t[(row0 + 8) * 64 + col]     = tf32r(v1.x);
                    g_dr_t[(row0 + 8) * 64 + col + 1] = tf32r(v1.y);
                }
            }
        }
    }
}

// ---------------- RMSNorm -> tf32-rounded u ----------------
__global__ void rmsnorm_kernel(const float* __restrict__ in,
                               const float* __restrict__ scale) {
    int l = blockIdx.x;
    int t = threadIdx.x;
    const float* row = in + (size_t)l * DM;
    float s = 0.f;
    for (int i = t; i < DM; i += 256) { float v = row[i]; s += v * v; }
    __shared__ float red[256];
    red[t] = s; __syncthreads();
    for (int o = 128; o > 0; o >>= 1) {
        if (t < o) red[t] += red[t + o];
        __syncthreads();
    }
    float inv = rsqrtf(red[0] * (1.f / DM) + 1e-6f);
    for (int i = t; i < DM; i += 256)
        g_u_t[(size_t)l * DM + i] = tf32r(row[i] * inv * scale[i]);
}

// ---------------- depthwise conv along d_inner + SiLU ----------------
__global__ void conv_silu_kernel(const float* __restrict__ cw,
                                 const float* __restrict__ cb) {
    int l = blockIdx.x;
    int t = threadIdx.x;
    __shared__ float xs[DI];
    const float4* src = (const float4*)(g_xres + (size_t)l * 2 * DI);
    float4* dst4 = (float4*)xs;
    for (int i = t; i < DI / 4; i += 256) dst4[i] = src[i];
    __syncthreads();
    float w0 = cw[l], w1 = cw[DI + l], w2 = cw[2 * DI + l], w3 = cw[3 * DI + l];
    float b = cb[l];
    for (int d = t; d < DI; d += 256) {
        float xm1 = (d > 0) ? xs[d - 1] : 0.f;
        float x0  = xs[d];
        float xp1 = (d < DI - 1) ? xs[d + 1] : 0.f;
        float xp2 = (d < DI - 2) ? xs[d + 2] : 0.f;
        float v = b + w0 * xm1 + w1 * x0 + w2 * xp1 + w3 * xp2;
        g_xconv[(size_t)l * DI + d] = v * (1.f / (1.f + __expf(-v)));
    }
}

// ---------------- selective scan, phase-split ----------------
__global__ void __launch_bounds__(256) scan_kernel(const float* __restrict__ A_log,
                                                   const float* __restrict__ Dp) {
    __shared__ float sdelta[16][16], sx[16][16], sB[16][16], sC[16][16], sres[16][16];
    __shared__ float sp[16 * 272 + 16];   // sp[i*272 + g*17 + n]
    int t = threadIdx.x;
    int g = t >> 4;
    int n = t & 15;
    int d0 = blockIdx.x * 16;
    int d  = d0 + g;

    float a = -expf(A_log[(size_t)d * DS + n]);
    float h = 0.f;
    int i2 = t >> 4;
    int g2 = t & 15;
    float Dd2 = Dp[d0 + g2];

    float pd = g_delta[(size_t)g * DI + d0 + n];
    float px = g_xconv[(size_t)g * DI + d0 + n];
    float pr = g_xres[(size_t)g * 2 * DI + DI + d0 + n];
    float pB = g_xdbl[(size_t)g * 96 + 64 + n];
    float pC = g_xdbl[(size_t)g * 96 + 80 + n];

    for (int l0 = 0; l0 < LSEQ; l0 += 16) {
        sdelta[g][n] = pd; sx[g][n] = px; sres[g][n] = pr; sB[g][n] = pB; sC[g][n] = pC;
        __syncthreads();
        if (l0 + 16 < LSEQ) {
            int l = l0 + 16 + g;
            pd = g_delta[(size_t)l * DI + d0 + n];
            px = g_xconv[(size_t)l * DI + d0 + n];
            pr = g_xres[(size_t)l * 2 * DI + DI + d0 + n];
            pB = g_xdbl[(size_t)l * 96 + 64 + n];
            pC = g_xdbl[(size_t)l * 96 + 80 + n];
        }
        #pragma unroll
        for (int i = 0; i < 16; ++i) {
            float dlt = sdelta[i][g];
            float dA  = __expf(dlt * a);
            h = fmaf(dA, h, dlt * sB[i][n] * sx[i][g]);
            sp[i * 272 + g * 17 + n] = h * sC[i][n];
        }
        __syncthreads();
        {
            const float* base = &sp[i2 * 272 + g2 * 17];
            float s0 = base[0] + base[1], s1 = base[2] + base[3];
            float s2 = base[4] + base[5], s3 = base[6] + base[7];
            float s4 = base[8] + base[9], s5 = base[10] + base[11];
            float s6 = base[12] + base[13], s7 = base[14] + base[15];
            float sum = ((s0 + s1) + (s2 + s3)) + ((s4 + s5) + (s6 + s7));
            float xv = sx[i2][g2];
            float r  = sres[i2][g2];
            float val = (sum + xv * Dd2) * (r / (1.f + __expf(-r)));
            g_y_t[(size_t)(l0 + i2) * DI + d0 + g2] = tf32r(val);
        }
        __syncthreads();
    }
}

// ---------------- launch ----------------
extern "C" void kernel_launch(void* const* d_in, const int* in_sizes, int n_in,
                              void* d_out, int out_size) {
    const float* inputs     = (const float*)d_in[0];
    const float* norm_scale = (const float*)d_in[1];
    const float* in_proj_w  = (const float*)d_in[2];
    const float* conv_w     = (const float*)d_in[3];
    const float* conv_b     = (const float*)d_in[4];
    const float* x_proj_w   = (const float*)d_in[5];
    const float* dt_proj_w  = (const float*)d_in[6];
    const float* dt_proj_b  = (const float*)d_in[7];
    const float* out_proj_w = (const float*)d_in[8];
    const float* A_log      = (const float*)d_in[9];
    const float* Dvec       = (const float*)d_in[10];
    float* out = (float*)d_out;

    void *p_xres, *p_xdbl, *p_delta, *p_u, *p_dr, *p_y;
    void *p_w1, *p_w2, *p_w3, *p_w4;
    cudaGetSymbolAddress(&p_xres, g_xres);
    cudaGetSymbolAddress(&p_xdbl, g_xdbl);
    cudaGetSymbolAddress(&p_delta, g_delta);
    cudaGetSymbolAddress(&p_u, g_u_t);
    cudaGetSymbolAddress(&p_dr, g_dr_t);
    cudaGetSymbolAddress(&p_y, g_y_t);
    cudaGetSymbolAddress(&p_w1, g_w1t);
    cudaGetSymbolAddress(&p_w2, g_w2t);
    cudaGetSymbolAddress(&p_w3, g_w3t);
    cudaGetSymbolAddress(&p_w4, g_w4t);

    const int SMEM256 = 3 * (18432 + 256 * 144);  // 165888
    const int SMEM128 = 3 * (18432 + 128 * 144);  // 110592
    cudaFuncSetAttribute(hgemm<256, 1>, cudaFuncAttributeMaxDynamicSharedMemorySize, SMEM256);
    cudaFuncSetAttribute(hgemm<128, 2>, cudaFuncAttributeMaxDynamicSharedMemorySize, SMEM128);

    // 0) weight transpose + tf32 rounding: W[K][N] -> Wt[N][K]
    conv_tr<<<dim3(4096 / 32, 1024 / 32), 256>>>(in_proj_w,  (float*)p_w1, DM, 2 * DI);
    conv_tr<<<dim3(96 / 32,   1024 / 32), 256>>>(x_proj_w,   (float*)p_w2, DM, 96);
    conv_tr<<<dim3(2048 / 32, 64 / 32),   256>>>(dt_proj_w,  (float*)p_w3, 64, DI);
    conv_tr<<<dim3(1024 / 32, 2048 / 32), 256>>>(out_proj_w, (float*)p_w4, DI, DM);

    // 1) RMSNorm -> u (tf32-rounded)
    rmsnorm_kernel<<<LSEQ, 256>>>(inputs, norm_scale);

    // 2) fused G1+G2: blocks 0..15 -> in_proj (xres), block 16 -> x_proj (xdbl + dr_t)
    hgemm<256, 1><<<dim3(17, 16), 256, SMEM256>>>(
        (const float*)p_u, DM,
        (const float*)p_w1, DM,
        (float*)p_xres, 2 * DI, nullptr, 0,
        DM, 2 * DI, 0, 16,
        (const float*)p_w2, DM, (float*)p_xdbl, 96, 96, 3);

    // 3) conv + silu
    conv_silu_kernel<<<LSEQ, 256>>>(conv_w, conv_b);

    // 4) G3: dr @ dt_proj_w + bias, softplus -> delta
    hgemm<256, 1><<<dim3(8, 16), 256, SMEM256>>>(
        (const float*)p_dr, 64,
        (const float*)p_w3, 64,
        (float*)p_delta, DI, dt_proj_b, 0,
        64, DI, 2, 1 << 30,
        nullptr, 0, nullptr, 0, 0, 0);

    // 5) scan -> y (tf32-rounded)
    scan_kernel<<<DI / 16, 256>>>(A_log, Dvec);

    // 6) G4: y @ out_proj_w + inputs -> out (128-wide tiles keep 128 CTAs)
    hgemm<128, 2><<<dim3(8, 16), 256, SMEM128>>>(
        (const float*)p_y, DI,
        (const float*)p_w4, DI,
        out, DM, inputs, DM,
        DI, DM, 1, 1 << 30,
        nullptr, 0, nullptr, 0, 0, 0);
}

// round 14
// speedup vs baseline: 1.0767x; 1.0767x over previous
#include <cuda_runtime.h>
#include <cuda_bf16.h>
#include <cstdint>

#define LSEQ 2048
#define DM   1024
#define DI   2048
#define DS   16

// ---------------- scratch ----------------
__device__ float g_xres[LSEQ * 2 * DI];   // G1 out (x | res), fp32
__device__ float g_xconv[LSEQ * DI];      // conv+silu, fp32
__device__ float g_xdbl[LSEQ * 96];       // x_proj out, fp32 (B,C for scan)
__device__ float g_delta[LSEQ * DI];      // softplus delta, fp32
__device__ float g_u_t[LSEQ * DM];        // rmsnorm out, tf32-rounded
__device__ float g_dr_t[LSEQ * 64];       // delta_r, tf32-rounded
__device__ float g_y_t[LSEQ * DI];        // scan out, tf32-rounded
// tf32-rounded weights, TRANSPOSED to [N][K]
__device__ float g_w1t[2 * DI * DM];
__device__ float g_w2t[96 * DM];
__device__ float g_w3t[DI * 64];
__device__ float g_w4t[DM * DI];

__device__ __forceinline__ float softplus_f(float x) {
    return fmaxf(x, 0.f) + log1pf(__expf(-fabsf(x)));
}
__device__ __forceinline__ float tf32r(float x) {
    uint32_t r;
    asm("cvt.rna.tf32.f32 %0, %1;" : "=r"(r) : "f"(x));
    return __uint_as_float(r);
}
__device__ __forceinline__ uint32_t smem_to_u32(const void* p) {
    uint32_t a;
    asm("{ .reg .u64 t; cvta.to.shared.u64 t, %1; cvt.u32.u64 %0, t; }" : "=r"(a) : "l"(p));
    return a;
}
__device__ __forceinline__ void ldsm4(uint32_t* r, uint32_t addr) {
    asm volatile("ldmatrix.sync.aligned.m8n8.x4.shared.b16 {%0,%1,%2,%3}, [%4];"
                 : "=r"(r[0]), "=r"(r[1]), "=r"(r[2]), "=r"(r[3]) : "r"(addr));
}
__device__ __forceinline__ void mma_tf32(float* c, const uint32_t* a, uint32_t b0, uint32_t b1) {
    asm volatile("mma.sync.aligned.m16n8k8.row.col.f32.tf32.tf32.f32 "
                 "{%0,%1,%2,%3}, {%4,%5,%6,%7}, {%8,%9}, {%0,%1,%2,%3};"
                 : "+f"(c[0]), "+f"(c[1]), "+f"(c[2]), "+f"(c[3])
                 : "r"(a[0]), "r"(a[1]), "r"(a[2]), "r"(a[3]), "r"(b0), "r"(b1));
}
__device__ __forceinline__ void cp16(uint32_t dst, const void* src, int sz) {
    asm volatile("cp.async.cg.shared.global [%0], [%1], 16, %2;" :: "r"(dst), "l"(src), "r"(sz));
}
#define CP_COMMIT() asm volatile("cp.async.commit_group;" ::: "memory")
#define CP_WAIT1()  asm volatile("cp.async.wait_group 1;" ::: "memory")

// ---------------- dual-matrix tiled transpose + tf32 round: W[K][N] -> Wt[N][K] ----------------
__global__ void __launch_bounds__(256) conv_tr2(
    const float* __restrict__ s1, float* __restrict__ d1, int K1, int N1, int nt1,
    const float* __restrict__ s2, float* __restrict__ d2, int K2, int N2) {
    __shared__ float tile[32][33];
    int t = blockIdx.x;
    const float* src; float* dst; int K, N;
    if (t < nt1) { src = s1; dst = d1; K = K1; N = N1; }
    else         { t -= nt1; src = s2; dst = d2; K = K2; N = N2; }
    int ncols = N >> 5;
    int n0 = (t % ncols) * 32, k0 = (t / ncols) * 32;
    int tx = threadIdx.x & 31, ty = threadIdx.x >> 5;  // 32 x 8
    #pragma unroll
    for (int j = 0; j < 4; ++j)
        tile[ty + j * 8][tx] = tf32r(src[(size_t)(k0 + ty + j * 8) * N + n0 + tx]);
    __syncthreads();
    #pragma unroll
    for (int j = 0; j < 4; ++j)
        dst[(size_t)(n0 + ty + j * 8) * K + k0 + tx] = tile[tx][ty + j * 8];
}

// ---------------- tf32 HMMA GEMM, templated N-tile, n-major B, all-ldsm ----------------
// NTILE=128: tile 128x128, warp 64x32, occ 2 (round-11 best config).
// A smem [128 m][36 w], B smem [NTILE n][36 w]; Bt gmem pre-transposed [N][K].
// epi: 0 plain, 1 +extra[r*lde+c], 2 softplus(acc+extra[c]), 3 plain + dr_t (c<64)
template <int NTILE, int MINB>
__global__ void __launch_bounds__(256, MINB) hgemm(
    const float* __restrict__ A, int lda,
    const float* Bt, int ldbt,
    float* C, int ldc, const float* __restrict__ extra, int lde,
    int K, int n_real, int epi, int nsplit,
    const float* B2t, int ldb2t, float* C2, int ldc2, int n2, int epi2)
{
    extern __shared__ char sm[];
    constexpr int STRW = 36;                 // words per row
    constexpr int STRB = STRW * 4;           // 144 bytes
    constexpr int APL  = 128 * STRB;         // A plane: 18432
    constexpr int BPL  = NTILE * STRB;       // B plane
    constexpr int STG  = APL + BPL;          // stage bytes
    constexpr int NTI  = NTILE / 32;         // 8-col n-tiles per warp
    constexpr int ITB  = NTILE / 32;         // B loader iterations

    int tid = threadIdx.x, wid = tid >> 5, lane = tid & 31;
    int bxi = blockIdx.x;
    int bx;
    if (bxi >= nsplit) {
        Bt = B2t; ldbt = ldb2t; C = C2; ldc = ldc2;
        n_real = n2; epi = epi2; bx = (bxi - nsplit) * NTILE;
    } else {
        bx = bxi * NTILE;
    }
    int by = blockIdx.y * 128;
    int wm = (wid >> 2) * 64, wn = (wid & 3) * (NTILE / 4);
    uint32_t smb = smem_to_u32(sm);

    float acc[4][NTI][4];
    #pragma unroll
    for (int i = 0; i < 4; ++i)
        #pragma unroll
        for (int j = 0; j < NTI; ++j)
            #pragma unroll
            for (int r = 0; r < 4; ++r) acc[i][j][r] = 0.f;

    int T = K >> 5;

    auto load_stage = [&](int s) {
        uint32_t base = smb + (s % 3) * STG;
        int kb = s << 5;
        #pragma unroll
        for (int i = 0; i < 4; ++i) {
            int pid = i * 256 + tid;
            int row = pid >> 3, ch = pid & 7;
            cp16(base + row * STRB + ch * 16,
                 A + (size_t)(by + row) * lda + kb + ch * 4, 16);
        }
        #pragma unroll
        for (int i = 0; i < ITB; ++i) {
            int pid = i * 256 + tid;
            int row = pid >> 3, ch = pid & 7;
            int n = bx + row;
            bool v = n < n_real;
            const float* src = v ? (Bt + (size_t)n * ldbt + kb + ch * 4) : Bt;
            cp16(base + APL + row * STRB + ch * 16, src, v ? 16 : 0);
        }
    };

    load_stage(0); CP_COMMIT();
    if (T > 1) { load_stage(1); }
    CP_COMMIT();

    int arow = wm + (lane & 15);
    int acol4 = (lane >> 4) << 2;
    int bgrp = lane >> 3, brr = lane & 7;
    int bcol = (bgrp >> 1) * 8 + brr;
    uint32_t bko = (uint32_t)((bgrp & 1) * 16);

    for (int s = 0; s < T; ++s) {
        CP_WAIT1();
        __syncthreads();
        if (s + 2 < T) load_stage(s + 2);
        CP_COMMIT();

        uint32_t bA = smb + (s % 3) * STG;
        uint32_t abase = bA + (uint32_t)(arow * STRW + acol4) * 4;
        uint32_t bbase = bA + APL + (uint32_t)((wn + bcol) * STRB) + bko;

        #pragma unroll
        for (int q = 0; q < 4; ++q) {
            uint32_t a[4][4];
            #pragma unroll
            for (int mt = 0; mt < 4; ++mt)
                ldsm4(a[mt], abase + (uint32_t)(mt * 16 * STRB + q * 32));
            uint32_t bf[NTI / 2][4];
            #pragma unroll
            for (int j = 0; j < NTI / 2; ++j)
                ldsm4(bf[j], bbase + (uint32_t)(j * 16 * STRB + q * 32));
            #pragma unroll
            for (int mt = 0; mt < 4; ++mt)
                #pragma unroll
                for (int j = 0; j < NTI / 2; ++j) {
                    mma_tf32(acc[mt][2 * j],     a[mt], bf[j][0], bf[j][1]);
                    mma_tf32(acc[mt][2 * j + 1], a[mt], bf[j][2], bf[j][3]);
                }
        }
    }

    // ---- epilogue ----
    #pragma unroll
    for (int mt = 0; mt < 4; ++mt) {
        #pragma unroll
        for (int nt = 0; nt < NTI; ++nt) {
            int row0 = by + wm + mt * 16 + (lane >> 2);
            int col  = bx + wn + nt * 8 + (lane & 3) * 2;
            if (col < n_real) {
                float* a = acc[mt][nt];
                float2 v0 = make_float2(a[0], a[1]);
                float2 v1 = make_float2(a[2], a[3]);
                if (epi == 1) {
                    float2 e0 = *(const float2*)(extra + (size_t)row0 * lde + col);
                    float2 e1 = *(const float2*)(extra + (size_t)(row0 + 8) * lde + col);
                    v0.x += e0.x; v0.y += e0.y;
                    v1.x += e1.x; v1.y += e1.y;
                } else if (epi == 2) {
                    float b0 = extra[col], b1 = extra[col + 1];
                    v0.x = softplus_f(v0.x + b0);
                    v0.y = softplus_f(v0.y + b1);
                    v1.x = softplus_f(v1.x + b0);
                    v1.y = softplus_f(v1.y + b1);
                }
                *(float2*)(C + (size_t)row0 * ldc + col)       = v0;
                *(float2*)(C + (size_t)(row0 + 8) * ldc + col) = v1;
                if (epi == 3 && col < 64) {
                    g_dr_t[row0 * 64 + col]           = tf32r(v0.x);
                    g_dr_t[row0 * 64 + col + 1]       = tf32r(v0.y);
                    g_dr_t[(row0 + 8) * 64 + col]     = tf32r(v1.x);
                    g_dr_t[(row0 + 8) * 64 + col + 1] = tf32r(v1.y);
                }
            }
        }
    }
}

// ---------------- RMSNorm -> tf32-rounded u ----------------
__global__ void rmsnorm_kernel(const float* __restrict__ in,
                               const float* __restrict__ scale) {
    int l = blockIdx.x;
    int t = threadIdx.x;
    const float* row = in + (size_t)l * DM;
    float s = 0.f;
    for (int i = t; i < DM; i += 256) { float v = row[i]; s += v * v; }
    __shared__ float red[256];
    red[t] = s; __syncthreads();
    for (int o = 128; o > 0; o >>= 1) {
        if (t < o) red[t] += red[t + o];
        __syncthreads();
    }
    float inv = rsqrtf(red[0] * (1.f / DM) + 1e-6f);
    for (int i = t; i < DM; i += 256)
        g_u_t[(size_t)l * DM + i] = tf32r(row[i] * inv * scale[i]);
}

// ---------------- depthwise conv along d_inner + SiLU ----------------
__global__ void conv_silu_kernel(const float* __restrict__ cw,
                                 const float* __restrict__ cb) {
    int l = blockIdx.x;
    int t = threadIdx.x;
    __shared__ float xs[DI];
    const float4* src = (const float4*)(g_xres + (size_t)l * 2 * DI);
    float4* dst4 = (float4*)xs;
    for (int i = t; i < DI / 4; i += 256) dst4[i] = src[i];
    __syncthreads();
    float w0 = cw[l], w1 = cw[DI + l], w2 = cw[2 * DI + l], w3 = cw[3 * DI + l];
    float b = cb[l];
    for (int d = t; d < DI; d += 256) {
        float xm1 = (d > 0) ? xs[d - 1] : 0.f;
        float x0  = xs[d];
        float xp1 = (d < DI - 1) ? xs[d + 1] : 0.f;
        float xp2 = (d < DI - 2) ? xs[d + 2] : 0.f;
        float v = b + w0 * xm1 + w1 * x0 + w2 * xp1 + w3 * xp2;
        g_xconv[(size_t)l * DI + d] = v * (1.f / (1.f + __expf(-v)));
    }
}

// ---------------- selective scan, phase-split ----------------
__global__ void __launch_bounds__(256) scan_kernel(const float* __restrict__ A_log,
                                                   const float* __restrict__ Dp) {
    __shared__ float sdelta[16][16], sx[16][16], sB[16][16], sC[16][16], sres[16][16];
    __shared__ float sp[16 * 272 + 16];   // sp[i*272 + g*17 + n]
    int t = threadIdx.x;
    int g = t >> 4;
    int n = t & 15;
    int d0 = blockIdx.x * 16;
    int d  = d0 + g;

    float a = -expf(A_log[(size_t)d * DS + n]);
    float h = 0.f;
    int i2 = t >> 4;
    int g2 = t & 15;
    float Dd2 = Dp[d0 + g2];

    float pd = g_delta[(size_t)g * DI + d0 + n];
    float px = g_xconv[(size_t)g * DI + d0 + n];
    float pr = g_xres[(size_t)g * 2 * DI + DI + d0 + n];
    float pB = g_xdbl[(size_t)g * 96 + 64 + n];
    float pC = g_xdbl[(size_t)g * 96 + 80 + n];

    for (int l0 = 0; l0 < LSEQ; l0 += 16) {
        sdelta[g][n] = pd; sx[g][n] = px; sres[g][n] = pr; sB[g][n] = pB; sC[g][n] = pC;
        __syncthreads();
        if (l0 + 16 < LSEQ) {
            int l = l0 + 16 + g;
            pd = g_delta[(size_t)l * DI + d0 + n];
            px = g_xconv[(size_t)l * DI + d0 + n];
            pr = g_xres[(size_t)l * 2 * DI + DI + d0 + n];
            pB = g_xdbl[(size_t)l * 96 + 64 + n];
            pC = g_xdbl[(size_t)l * 96 + 80 + n];
        }
        #pragma unroll
        for (int i = 0; i < 16; ++i) {
            float dlt = sdelta[i][g];
            float dA  = __expf(dlt * a);
            h = fmaf(dA, h, dlt * sB[i][n] * sx[i][g]);
            sp[i * 272 + g * 17 + n] = h * sC[i][n];
        }
        __syncthreads();
        {
            const float* base = &sp[i2 * 272 + g2 * 17];
            float s0 = base[0] + base[1], s1 = base[2] + base[3];
            float s2 = base[4] + base[5], s3 = base[6] + base[7];
            float s4 = base[8] + base[9], s5 = base[10] + base[11];
            float s6 = base[12] + base[13], s7 = base[14] + base[15];
            float sum = ((s0 + s1) + (s2 + s3)) + ((s4 + s5) + (s6 + s7));
            float xv = sx[i2][g2];
            float r  = sres[i2][g2];
            float val = (sum + xv * Dd2) * (r / (1.f + __expf(-r)));
            g_y_t[(size_t)(l0 + i2) * DI + d0 + g2] = tf32r(val);
        }
        __syncthreads();
    }
}

// ---------------- launch ----------------
extern "C" void kernel_launch(void* const* d_in, const int* in_sizes, int n_in,
                              void* d_out, int out_size) {
    const float* inputs     = (const float*)d_in[0];
    const float* norm_scale = (const float*)d_in[1];
    const float* in_proj_w  = (const float*)d_in[2];
    const float* conv_w     = (const float*)d_in[3];
    const float* conv_b     = (const float*)d_in[4];
    const float* x_proj_w   = (const float*)d_in[5];
    const float* dt_proj_w  = (const float*)d_in[6];
    const float* dt_proj_b  = (const float*)d_in[7];
    const float* out_proj_w = (const float*)d_in[8];
    const float* A_log      = (const float*)d_in[9];
    const float* Dvec       = (const float*)d_in[10];
    float* out = (float*)d_out;

    void *p_xres, *p_xdbl, *p_delta, *p_u, *p_dr, *p_y;
    void *p_w1, *p_w2, *p_w3, *p_w4;
    cudaGetSymbolAddress(&p_xres, g_xres);
    cudaGetSymbolAddress(&p_xdbl, g_xdbl);
    cudaGetSymbolAddress(&p_delta, g_delta);
    cudaGetSymbolAddress(&p_u, g_u_t);
    cudaGetSymbolAddress(&p_dr, g_dr_t);
    cudaGetSymbolAddress(&p_y, g_y_t);
    cudaGetSymbolAddress(&p_w1, g_w1t);
    cudaGetSymbolAddress(&p_w2, g_w2t);
    cudaGetSymbolAddress(&p_w3, g_w3t);
    cudaGetSymbolAddress(&p_w4, g_w4t);

    const int SMEM128 = 3 * (18432 + 128 * 144);  // 110592
    cudaFuncSetAttribute(hgemm<128, 2>, cudaFuncAttributeMaxDynamicSharedMemorySize, SMEM128);

    // 0) weight transpose + tf32 rounding, 2 fused launches
    //    launch 1: w1 [1024x4096] (4096 tiles) + w2 [1024x96] (96 tiles)
    conv_tr2<<<4096 + 96, 256>>>(in_proj_w, (float*)p_w1, DM, 2 * DI, 4096,
                                 x_proj_w, (float*)p_w2, DM, 96);
    //    launch 2: w3 [64x2048] (128 tiles) + w4 [2048x1024] (2048 tiles)
    conv_tr2<<<128 + 2048, 256>>>(dt_proj_w, (float*)p_w3, 64, DI, 128,
                                  out_proj_w, (float*)p_w4, DI, DM);

    // 1) RMSNorm -> u (tf32-rounded)   [my launch #3]
    rmsnorm_kernel<<<LSEQ, 256>>>(inputs, norm_scale);

    // 2) fused G1+G2 [my launch #4 — ncu capture slot]
    hgemm<128, 2><<<dim3(33, 16), 256, SMEM128>>>(
        (const float*)p_u, DM,
        (const float*)p_w1, DM,
        (float*)p_xres, 2 * DI, nullptr, 0,
        DM, 2 * DI, 0, 32,
        (const float*)p_w2, DM, (float*)p_xdbl, 96, 96, 3);

    // 3) conv + silu
    conv_silu_kernel<<<LSEQ, 256>>>(conv_w, conv_b);

    // 4) G3: dr @ dt_proj_w + bias, softplus -> delta
    hgemm<128, 2><<<dim3(16, 16), 256, SMEM128>>>(
        (const float*)p_dr, 64,
        (const float*)p_w3, 64,
        (float*)p_delta, DI, dt_proj_b, 0,
        64, DI, 2, 1 << 30,
        nullptr, 0, nullptr, 0, 0, 0);

    // 5) scan -> y (tf32-rounded)
    scan_kernel<<<DI / 16, 256>>>(A_log, Dvec);

    // 6) G4: y @ out_proj_w + inputs -> out
    hgemm<128, 2><<<dim3(8, 16), 256, SMEM128>>>(
        (const float*)p_y, DI,
        (const float*)p_w4, DI,
        out, DM, inputs, DM,
        DI, DM, 1, 1 << 30,
        nullptr, 0, nullptr, 0, 0, 0);
}

// round 16
// speedup vs baseline: 1.1574x; 1.0750x over previous
#include <cuda_runtime.h>
#include <cuda_bf16.h>
#include <cstdint>

#define LSEQ 2048
#define DM   1024
#define DI   2048
#define DS   16

// ---------------- scratch ----------------
__device__ float g_xres[LSEQ * 2 * DI];   // G1 out (x | res), fp32
__device__ float g_xconv[LSEQ * DI];      // conv+silu, fp32
__device__ float g_xdbl[LSEQ * 96];       // x_proj out, fp32 (B,C for scan)
__device__ float g_delta[LSEQ * DI];      // softplus delta, fp32
__device__ float g_u_t[LSEQ * DM];        // rmsnorm out, tf32-rounded
__device__ float g_dr_t[LSEQ * 64];       // delta_r, tf32-rounded
__device__ float g_y_t[LSEQ * DI];        // scan out, tf32-rounded
__device__ float g_p4[LSEQ * DM];         // G4 split-K partial
// tf32-rounded weights, TRANSPOSED to [N][K]
__device__ float g_w1t[2 * DI * DM];
__device__ float g_w2t[96 * DM];
__device__ float g_w3t[DI * 64];
__device__ float g_w4t[DM * DI];

__device__ __forceinline__ float softplus_f(float x) {
    return fmaxf(x, 0.f) + log1pf(__expf(-fabsf(x)));
}
__device__ __forceinline__ float tf32r(float x) {
    uint32_t r;
    asm("cvt.rna.tf32.f32 %0, %1;" : "=r"(r) : "f"(x));
    return __uint_as_float(r);
}
__device__ __forceinline__ uint32_t smem_to_u32(const void* p) {
    uint32_t a;
    asm("{ .reg .u64 t; cvta.to.shared.u64 t, %1; cvt.u32.u64 %0, t; }" : "=r"(a) : "l"(p));
    return a;
}
__device__ __forceinline__ void ldsm4(uint32_t* r, uint32_t addr) {
    asm volatile("ldmatrix.sync.aligned.m8n8.x4.shared.b16 {%0,%1,%2,%3}, [%4];"
                 : "=r"(r[0]), "=r"(r[1]), "=r"(r[2]), "=r"(r[3]) : "r"(addr));
}
__device__ __forceinline__ void mma_tf32(float* c, const uint32_t* a, uint32_t b0, uint32_t b1) {
    asm volatile("mma.sync.aligned.m16n8k8.row.col.f32.tf32.tf32.f32 "
                 "{%0,%1,%2,%3}, {%4,%5,%6,%7}, {%8,%9}, {%0,%1,%2,%3};"
                 : "+f"(c[0]), "+f"(c[1]), "+f"(c[2]), "+f"(c[3])
                 : "r"(a[0]), "r"(a[1]), "r"(a[2]), "r"(a[3]), "r"(b0), "r"(b1));
}
__device__ __forceinline__ void cp16(uint32_t dst, const void* src, int sz) {
    asm volatile("cp.async.cg.shared.global [%0], [%1], 16, %2;" :: "r"(dst), "l"(src), "r"(sz));
}
#define CP_COMMIT() asm volatile("cp.async.commit_group;" ::: "memory")
#define CP_WAIT1()  asm volatile("cp.async.wait_group 1;" ::: "memory")

// ---------------- dual-matrix tiled transpose + tf32 round: W[K][N] -> Wt[N][K] ----------------
__global__ void __launch_bounds__(256) conv_tr2(
    const float* __restrict__ s1, float* __restrict__ d1, int K1, int N1, int nt1,
    const float* __restrict__ s2, float* __restrict__ d2, int K2, int N2) {
    __shared__ float tile[32][33];
    int t = blockIdx.x;
    const float* src; float* dst; int K, N;
    if (t < nt1) { src = s1; dst = d1; K = K1; N = N1; }
    else         { t -= nt1; src = s2; dst = d2; K = K2; N = N2; }
    int ncols = N >> 5;
    int n0 = (t % ncols) * 32, k0 = (t / ncols) * 32;
    int tx = threadIdx.x & 31, ty = threadIdx.x >> 5;  // 32 x 8
    #pragma unroll
    for (int j = 0; j < 4; ++j)
        tile[ty + j * 8][tx] = tf32r(src[(size_t)(k0 + ty + j * 8) * N + n0 + tx]);
    __syncthreads();
    #pragma unroll
    for (int j = 0; j < 4; ++j)
        dst[(size_t)(n0 + ty + j * 8) * K + k0 + tx] = tile[tx][ty + j * 8];
}

// ---------------- tf32 HMMA GEMM, n-major B, all-ldsm, interleaved prefetch ----------------
// NTILE=128: tile 128x128, warp 64x32, occ 2.
// Region switch (bxi >= nsplit): B/C swap + A k-offset (enables single-launch split-K).
// epi: 0 plain, 1 +extra[r*lde+c], 2 softplus(acc+extra[c]), 3 plain + dr_t (c<64)
template <int NTILE, int MINB>
__global__ void __launch_bounds__(256, MINB) hgemm(
    const float* __restrict__ A, int lda,
    const float* Bt, int ldbt,
    float* C, int ldc, const float* __restrict__ extra, int lde,
    int K, int n_real, int epi, int nsplit,
    const float* B2t, int ldb2t, float* C2, int ldc2, int n2, int epi2, int aoff2)
{
    extern __shared__ char sm[];
    constexpr int STRW = 36;                 // words per row
    constexpr int STRB = STRW * 4;           // 144 bytes
    constexpr int APL  = 128 * STRB;         // A plane: 18432
    constexpr int BPL  = NTILE * STRB;       // B plane
    constexpr int STG  = APL + BPL;          // stage bytes
    constexpr int NTI  = NTILE / 32;         // 8-col n-tiles per warp
    constexpr int ITB  = NTILE / 32;         // B loader iterations

    int tid = threadIdx.x, wid = tid >> 5, lane = tid & 31;
    int bxi = blockIdx.x;
    int bx;
    if (bxi >= nsplit) {
        Bt = B2t; ldbt = ldb2t; C = C2; ldc = ldc2;
        n_real = n2; epi = epi2; A += aoff2;
        bx = (bxi - nsplit) * NTILE;
    } else {
        bx = bxi * NTILE;
    }
    int by = blockIdx.y * 128;
    int wm = (wid >> 2) * 64, wn = (wid & 3) * (NTILE / 4);
    uint32_t smb = smem_to_u32(sm);

    float acc[4][NTI][4];
    #pragma unroll
    for (int i = 0; i < 4; ++i)
        #pragma unroll
        for (int j = 0; j < NTI; ++j)
            #pragma unroll
            for (int r = 0; r < 4; ++r) acc[i][j][r] = 0.f;

    int T = K >> 5;

    auto load_A = [&](int s) {
        uint32_t base = smb + (s % 3) * STG;
        int kb = s << 5;
        #pragma unroll
        for (int i = 0; i < 4; ++i) {
            int pid = i * 256 + tid;
            int row = pid >> 3, ch = pid & 7;
            cp16(base + row * STRB + ch * 16,
                 A + (size_t)(by + row) * lda + kb + ch * 4, 16);
        }
    };
    auto load_B = [&](int s) {
        uint32_t base = smb + (s % 3) * STG;
        int kb = s << 5;
        #pragma unroll
        for (int i = 0; i < ITB; ++i) {
            int pid = i * 256 + tid;
            int row = pid >> 3, ch = pid & 7;
            int n = bx + row;
            bool v = n < n_real;
            const float* src = v ? (Bt + (size_t)n * ldbt + kb + ch * 4) : Bt;
            cp16(base + APL + row * STRB + ch * 16, src, v ? 16 : 0);
        }
    };

    load_A(0); load_B(0); CP_COMMIT();
    if (T > 1) { load_A(1); load_B(1); }
    CP_COMMIT();

    int arow = wm + (lane & 15);
    int acol4 = (lane >> 4) << 2;
    int bgrp = lane >> 3, brr = lane & 7;
    int bcol = (bgrp >> 1) * 8 + brr;
    uint32_t bko = (uint32_t)((bgrp & 1) * 16);

    for (int s = 0; s < T; ++s) {
        CP_WAIT1();
        __syncthreads();
        bool pf = (s + 2 < T);

        uint32_t bA = smb + (s % 3) * STG;
        uint32_t abase = bA + (uint32_t)(arow * STRW + acol4) * 4;
        uint32_t bbase = bA + APL + (uint32_t)((wn + bcol) * STRB) + bko;

        #pragma unroll
        for (int q = 0; q < 4; ++q) {
            uint32_t a[4][4];
            #pragma unroll
            for (int mt = 0; mt < 4; ++mt)
                ldsm4(a[mt], abase + (uint32_t)(mt * 16 * STRB + q * 32));
            uint32_t bf[NTI / 2][4];
            #pragma unroll
            for (int j = 0; j < NTI / 2; ++j)
                ldsm4(bf[j], bbase + (uint32_t)(j * 16 * STRB + q * 32));
            #pragma unroll
            for (int mt = 0; mt < 4; ++mt)
                #pragma unroll
                for (int j = 0; j < NTI / 2; ++j) {
                    mma_tf32(acc[mt][2 * j],     a[mt], bf[j][0], bf[j][1]);
                    mma_tf32(acc[mt][2 * j + 1], a[mt], bf[j][2], bf[j][3]);
                }
            // interleaved prefetch: spread the s+2 load across the q-loop
            if (q == 0 && pf) load_A(s + 2);
            if (q == 1) {
                if (pf) load_B(s + 2);
                CP_COMMIT();   // exactly one commit per iteration (may be empty)
            }
        }
    }

    // ---- epilogue ----
    #pragma unroll
    for (int mt = 0; mt < 4; ++mt) {
        #pragma unroll
        for (int nt = 0; nt < NTI; ++nt) {
            int row0 = by + wm + mt * 16 + (lane >> 2);
            int col  = bx + wn + nt * 8 + (lane & 3) * 2;
            if (col < n_real) {
                float* a = acc[mt][nt];
                float2 v0 = make_float2(a[0], a[1]);
                float2 v1 = make_float2(a[2], a[3]);
                if (epi == 1) {
                    float2 e0 = *(const float2*)(extra + (size_t)row0 * lde + col);
                    float2 e1 = *(const float2*)(extra + (size_t)(row0 + 8) * lde + col);
                    v0.x += e0.x; v0.y += e0.y;
                    v1.x += e1.x; v1.y += e1.y;
                } else if (epi == 2) {
                    float b0 = extra[col], b1 = extra[col + 1];
                    v0.x = softplus_f(v0.x + b0);
                    v0.y = softplus_f(v0.y + b1);
                    v1.x = softplus_f(v1.x + b0);
                    v1.y = softplus_f(v1.y + b1);
                }
                *(float2*)(C + (size_t)row0 * ldc + col)       = v0;
                *(float2*)(C + (size_t)(row0 + 8) * ldc + col) = v1;
                if (epi == 3 && col < 64) {
                    g_dr_t[row0 * 64 + col]           = tf32r(v0.x);
                    g_dr_t[row0 * 64 + col + 1]       = tf32r(v0.y);
                    g_dr_t[(row0 + 8) * 64 + col]     = tf32r(v1.x);
                    g_dr_t[(row0 + 8) * 64 + col + 1] = tf32r(v1.y);
                }
            }
        }
    }
}

// ---------------- split-K reduce: out += partial + residual ----------------
__global__ void __launch_bounds__(256) reduce_add(float* __restrict__ out,
                                                  const float* __restrict__ part,
                                                  const float* __restrict__ resid) {
    int i = blockIdx.x * blockDim.x + threadIdx.x;
    float4 a = ((const float4*)out)[i];
    float4 b = ((const float4*)part)[i];
    float4 c = ((const float4*)resid)[i];
    a.x += b.x + c.x; a.y += b.y + c.y; a.z += b.z + c.z; a.w += b.w + c.w;
    ((float4*)out)[i] = a;
}

// ---------------- RMSNorm -> tf32-rounded u ----------------
__global__ void rmsnorm_kernel(const float* __restrict__ in,
                               const float* __restrict__ scale) {
    int l = blockIdx.x;
    int t = threadIdx.x;
    const float* row = in + (size_t)l * DM;
    float s = 0.f;
    for (int i = t; i < DM; i += 256) { float v = row[i]; s += v * v; }
    __shared__ float red[256];
    red[t] = s; __syncthreads();
    for (int o = 128; o > 0; o >>= 1) {
        if (t < o) red[t] += red[t + o];
        __syncthreads();
    }
    float inv = rsqrtf(red[0] * (1.f / DM) + 1e-6f);
    for (int i = t; i < DM; i += 256)
        g_u_t[(size_t)l * DM + i] = tf32r(row[i] * inv * scale[i]);
}

// ---------------- depthwise conv along d_inner + SiLU ----------------
__global__ void conv_silu_kernel(const float* __restrict__ cw,
                                 const float* __restrict__ cb) {
    int l = blockIdx.x;
    int t = threadIdx.x;
    __shared__ float xs[DI];
    const float4* src = (const float4*)(g_xres + (size_t)l * 2 * DI);
    float4* dst4 = (float4*)xs;
    for (int i = t; i < DI / 4; i += 256) dst4[i] = src[i];
    __syncthreads();
    float w0 = cw[l], w1 = cw[DI + l], w2 = cw[2 * DI + l], w3 = cw[3 * DI + l];
    float b = cb[l];
    for (int d = t; d < DI; d += 256) {
        float xm1 = (d > 0) ? xs[d - 1] : 0.f;
        float x0  = xs[d];
        float xp1 = (d < DI - 1) ? xs[d + 1] : 0.f;
        float xp2 = (d < DI - 2) ? xs[d + 2] : 0.f;
        float v = b + w0 * xm1 + w1 * x0 + w2 * xp1 + w3 * xp2;
        g_xconv[(size_t)l * DI + d] = v * (1.f / (1.f + __expf(-v)));
    }
}

// ---------------- selective scan, phase-split ----------------
__global__ void __launch_bounds__(256) scan_kernel(const float* __restrict__ A_log,
                                                   const float* __restrict__ Dp) {
    __shared__ float sdelta[16][16], sx[16][16], sB[16][16], sC[16][16], sres[16][16];
    __shared__ float sp[16 * 272 + 16];   // sp[i*272 + g*17 + n]
    int t = threadIdx.x;
    int g = t >> 4;
    int n = t & 15;
    int d0 = blockIdx.x * 16;
    int d  = d0 + g;

    float a = -expf(A_log[(size_t)d * DS + n]);
    float h = 0.f;
    int i2 = t >> 4;
    int g2 = t & 15;
    float Dd2 = Dp[d0 + g2];

    float pd = g_delta[(size_t)g * DI + d0 + n];
    float px = g_xconv[(size_t)g * DI + d0 + n];
    float pr = g_xres[(size_t)g * 2 * DI + DI + d0 + n];
    float pB = g_xdbl[(size_t)g * 96 + 64 + n];
    float pC = g_xdbl[(size_t)g * 96 + 80 + n];

    for (int l0 = 0; l0 < LSEQ; l0 += 16) {
        sdelta[g][n] = pd; sx[g][n] = px; sres[g][n] = pr; sB[g][n] = pB; sC[g][n] = pC;
        __syncthreads();
        if (l0 + 16 < LSEQ) {
            int l = l0 + 16 + g;
            pd = g_delta[(size_t)l * DI + d0 + n];
            px = g_xconv[(size_t)l * DI + d0 + n];
            pr = g_xres[(size_t)l * 2 * DI + DI + d0 + n];
            pB = g_xdbl[(size_t)l * 96 + 64 + n];
            pC = g_xdbl[(size_t)l * 96 + 80 + n];
        }
        #pragma unroll
        for (int i = 0; i < 16; ++i) {
            float dlt = sdelta[i][g];
            float dA  = __expf(dlt * a);
            h = fmaf(dA, h, dlt * sB[i][n] * sx[i][g]);
            sp[i * 272 + g * 17 + n] = h * sC[i][n];
        }
        __syncthreads();
        {
            const float* base = &sp[i2 * 272 + g2 * 17];
            float s0 = base[0] + base[1], s1 = base[2] + base[3];
            float s2 = base[4] + base[5], s3 = base[6] + base[7];
            float s4 = base[8] + base[9], s5 = base[10] + base[11];
            float s6 = base[12] + base[13], s7 = base[14] + base[15];
            float sum = ((s0 + s1) + (s2 + s3)) + ((s4 + s5) + (s6 + s7));
            float xv = sx[i2][g2];
            float r  = sres[i2][g2];
            float val = (sum + xv * Dd2) * (r / (1.f + __expf(-r)));
            g_y_t[(size_t)(l0 + i2) * DI + d0 + g2] = tf32r(val);
        }
        __syncthreads();
    }
}

// ---------------- launch ----------------
extern "C" void kernel_launch(void* const* d_in, const int* in_sizes, int n_in,
                              void* d_out, int out_size) {
    const float* inputs     = (const float*)d_in[0];
    const float* norm_scale = (const float*)d_in[1];
    const float* in_proj_w  = (const float*)d_in[2];
    const float* conv_w     = (const float*)d_in[3];
    const float* conv_b     = (const float*)d_in[4];
    const float* x_proj_w   = (const float*)d_in[5];
    const float* dt_proj_w  = (const float*)d_in[6];
    const float* dt_proj_b  = (const float*)d_in[7];
    const float* out_proj_w = (const float*)d_in[8];
    const float* A_log      = (const float*)d_in[9];
    const float* Dvec       = (const float*)d_in[10];
    float* out = (float*)d_out;

    void *p_xres, *p_xdbl, *p_delta, *p_u, *p_dr, *p_y, *p_p4;
    void *p_w1, *p_w2, *p_w3, *p_w4;
    cudaGetSymbolAddress(&p_xres, g_xres);
    cudaGetSymbolAddress(&p_xdbl, g_xdbl);
    cudaGetSymbolAddress(&p_delta, g_delta);
    cudaGetSymbolAddress(&p_u, g_u_t);
    cudaGetSymbolAddress(&p_dr, g_dr_t);
    cudaGetSymbolAddress(&p_y, g_y_t);
    cudaGetSymbolAddress(&p_p4, g_p4);
    cudaGetSymbolAddress(&p_w1, g_w1t);
    cudaGetSymbolAddress(&p_w2, g_w2t);
    cudaGetSymbolAddress(&p_w3, g_w3t);
    cudaGetSymbolAddress(&p_w4, g_w4t);

    const int SMEM128 = 3 * (18432 + 128 * 144);  // 110592
    cudaFuncSetAttribute(hgemm<128, 2>, cudaFuncAttributeMaxDynamicSharedMemorySize, SMEM128);

    // 0) weight transpose + tf32 rounding, 2 fused launches
    conv_tr2<<<4096 + 96, 256>>>(in_proj_w, (float*)p_w1, DM, 2 * DI, 4096,
                                 x_proj_w, (float*)p_w2, DM, 96);
    conv_tr2<<<128 + 2048, 256>>>(dt_proj_w, (float*)p_w3, 64, DI, 128,
                                  out_proj_w, (float*)p_w4, DI, DM);

    // 1) RMSNorm -> u (tf32-rounded)   [launch #3]
    rmsnorm_kernel<<<LSEQ, 256>>>(inputs, norm_scale);

    // 2) fused G1+G2 [launch #4 — ncu capture slot]
    hgemm<128, 2><<<dim3(33, 16), 256, SMEM128>>>(
        (const float*)p_u, DM,
        (const float*)p_w1, DM,
        (float*)p_xres, 2 * DI, nullptr, 0,
        DM, 2 * DI, 0, 32,
        (const float*)p_w2, DM, (float*)p_xdbl, 96, 96, 3, 0);

    // 3) conv + silu
    conv_silu_kernel<<<LSEQ, 256>>>(conv_w, conv_b);

    // 4) G3: dr @ dt_proj_w + bias, softplus -> delta
    hgemm<128, 2><<<dim3(16, 16), 256, SMEM128>>>(
        (const float*)p_dr, 64,
        (const float*)p_w3, 64,
        (float*)p_delta, DI, dt_proj_b, 0,
        64, DI, 2, 1 << 30,
        nullptr, 0, nullptr, 0, 0, 0, 0);

    // 5) scan -> y (tf32-rounded)
    scan_kernel<<<DI / 16, 256>>>(A_log, Dvec);

    // 6) G4 split-K=2 in one launch: bxi 0..7 -> K[0,1024) -> out (plain);
    //    bxi 8..15 -> K[1024,2048) -> g_p4 (A and Bt offset by 1024 k-columns)
    hgemm<128, 2><<<dim3(16, 16), 256, SMEM128>>>(
        (const float*)p_y, DI,
        (const float*)p_w4, DI,
        out, DM, nullptr, 0,
        1024, DM, 0, 8,
        (const float*)p_w4 + 1024, DI, (float*)p_p4, DM, DM, 0, 1024);

    // 7) reduce: out += partial + inputs
    reduce_add<<<LSEQ * DM / 4 / 256, 256>>>(out, (const float*)p_p4, inputs);
}